// round 2
// baseline (speedup 1.0000x reference)
#include <cuda_runtime.h>
#include <math.h>

#define HW    65536
#define FDIM  64
#define BDIM  8
#define NSEG  33
#define CP    1024      // pixels per block chunk
#define NCHUNK 64
#define TP    128       // tile pixels
#define NT    (CP/TP)   // 8 tiles per chunk
#define PITCH 132       // smem tile row pitch (floats), 16B aligned rows

// cross-block accumulator: monotone-uint-mapped float max
__device__ unsigned g_scratch[BDIM * NSEG * FDIM];

__device__ __forceinline__ unsigned fmap(float x) {
    unsigned b = __float_as_uint(x);
    return (b & 0x80000000u) ? ~b : (b | 0x80000000u);
}
__device__ __forceinline__ float funmap(unsigned u) {
    return __uint_as_float((u & 0x80000000u) ? (u ^ 0x80000000u) : ~u);
}

__global__ void init_kernel() {
    int idx = blockIdx.x * 256 + threadIdx.x;
    if (idx < BDIM * NSEG * FDIM) g_scratch[idx] = 0x007FFFFFu;  // fmap(-inf)
}

// Segment-max: grid (64 chunks, 8 batches), 256 threads = 64 features x 4 subchunks.
// Smem-staged tiles for coalesced loads; private accumulator columns (no atomics
// in the hot loop); swizzled read order for conflict-free LDS.
__global__ __launch_bounds__(256)
void segmax_kernel(const float* __restrict__ enc, const int* __restrict__ masks) {
    extern __shared__ float sm[];
    float* tile = sm;                         // 64 * 132 floats
    float* acc  = sm + FDIM * PITCH;          // 33 * 256 floats
    int*   ids  = (int*)(acc + NSEG * 256);   // 1024 ints

    const int tid = threadIdx.x;
    const int f   = tid & 63;
    const int s   = tid >> 6;
    const int gp0 = blockIdx.x * CP;
    const int b   = blockIdx.y;

    for (int idx = tid; idx < NSEG * 256; idx += 256) acc[idx] = -INFINITY;

    const int* mb = masks + b * HW + gp0;
    for (int idx = tid; idx < CP; idx += 256) ids[idx] = mb[idx];

    const float* encB = enc + (size_t)b * FDIM * HW;

    float4 pre[8];
    // prefetch tile 0
    #pragma unroll
    for (int k = 0; k < 8; k++) {
        int li  = tid + k * 256;
        int row = li >> 5;
        int c4  = li & 31;
        pre[k] = __ldg((const float4*)(encB + row * HW + gp0 + c4 * 4));
    }

    for (int t = 0; t < NT; t++) {
        __syncthreads();   // previous tile fully consumed
        #pragma unroll
        for (int k = 0; k < 8; k++) {
            int li  = tid + k * 256;
            int row = li >> 5;
            int c4  = li & 31;
            *(float4*)(tile + row * PITCH + c4 * 4) = pre[k];
        }
        if (t + 1 < NT) {
            int p0 = gp0 + (t + 1) * TP;
            #pragma unroll
            for (int k = 0; k < 8; k++) {
                int li  = tid + k * 256;
                int row = li >> 5;
                int c4  = li & 31;
                pre[k] = __ldg((const float4*)(encB + row * HW + p0 + c4 * 4));
            }
        }
        __syncthreads();   // tile visible

        const float* tf  = tile + f * PITCH + s * 32;
        const int*   idp = ids + t * TP + s * 32;
        #pragma unroll
        for (int i = 0; i < 32; i++) {
            int   px = (i + f) & 31;          // bank-swizzled order: conflict-free
            int   id = idp[px];
            float v  = tf[px];
            float* ap = acc + id * 256 + tid; // private column: no race
            *ap = fmaxf(*ap, v);
        }
    }

    __syncthreads();
    unsigned* gs = g_scratch + b * NSEG * FDIM;
    for (int idx = tid; idx < NSEG * FDIM; idx += 256) {
        int seg = idx >> 6;
        int ff  = idx & 63;
        const float* a = acc + seg * 256 + ff;
        float m = fmaxf(fmaxf(a[0], a[64]), fmaxf(a[128], a[192]));
        atomicMax(gs + idx, fmap(m));
    }
}

// MLP: grid (4, 8), 256 threads; one (i,j) pair per thread, all 32 hidden dims
// in registers, broadcast float4 W1 reads from smem.
__global__ __launch_bounds__(256)
void mlp_kernel(const float* __restrict__ W1, const float* __restrict__ b1,
                const float* __restrict__ W2, const float* __restrict__ b2,
                float* __restrict__ out) {
    __shared__ float vs[32 * 65];     // pitch 65: kills 32-way conflict on vj stream
    __shared__ float W1s[128 * 32];
    __shared__ float W2s[128];
    __shared__ float b1s[32];
    __shared__ float b2s[4];

    const int tid = threadIdx.x;
    const int b   = blockIdx.y;
    const unsigned* gs = g_scratch + b * NSEG * FDIM;

    for (int idx = tid; idx < 32 * 64; idx += 256) {
        int n = idx >> 6, ff = idx & 63;
        float v = funmap(gs[(n + 1) * 64 + ff]);   // drop segment 0
        vs[n * 65 + ff] = v;
        if (blockIdx.x == 0) out[b * 2048 + idx] = v;   // vectors output
    }
    for (int idx = tid; idx < 4096; idx += 256) W1s[idx] = W1[idx];
    if (tid < 128) W2s[tid] = W2[tid];
    if (tid < 32)  b1s[tid] = b1[tid];
    if (tid < 4)   b2s[tid] = b2[tid];
    __syncthreads();

    const int pair = blockIdx.x * 256 + tid;   // 0..1023
    const int i = pair >> 5, j = pair & 31;
    const float* vi = vs + i * 65;
    const float* vj = vs + j * 65;

    float acc[32];
    #pragma unroll
    for (int h = 0; h < 32; h++) acc[h] = b1s[h];

    #pragma unroll 8
    for (int d = 0; d < 64; d++) {
        float a = vi[d], c = vj[d];
        const float4* w1 = (const float4*)(W1s + d * 32);
        const float4* w2 = (const float4*)(W1s + (64 + d) * 32);
        #pragma unroll
        for (int q = 0; q < 8; q++) {
            float4 x = w1[q], y = w2[q];
            acc[4*q+0] += a * x.x + c * y.x;
            acc[4*q+1] += a * x.y + c * y.y;
            acc[4*q+2] += a * x.z + c * y.z;
            acc[4*q+3] += a * x.w + c * y.w;
        }
    }

    // connections[b][c][j][i] = sigmoid(h @ W2 + b2)[c]
    float* oc = out + 16384 + b * 4096 + j * 32 + i;
    #pragma unroll
    for (int cc = 0; cc < 4; cc++) {
        float o = b2s[cc];
        #pragma unroll
        for (int h = 0; h < 32; h++) o += acc[h] * W2s[h * 4 + cc];
        oc[cc * 1024] = 1.0f / (1.0f + expf(-o));
    }
}

extern "C" void kernel_launch(void* const* d_in, const int* in_sizes, int n_in,
                              void* d_out, int out_size) {
    const float* enc   = (const float*)d_in[0];
    const int*   masks = (const int*)d_in[1];
    const float* W1    = (const float*)d_in[2];
    const float* b1    = (const float*)d_in[3];
    const float* W2    = (const float*)d_in[4];
    const float* b2    = (const float*)d_in[5];
    float* out = (float*)d_out;

    init_kernel<<<(BDIM * NSEG * FDIM + 255) / 256, 256>>>();

    const int smem = (FDIM * PITCH + NSEG * 256) * 4 + CP * 4;   // 71680 B
    cudaFuncSetAttribute(segmax_kernel,
                         cudaFuncAttributeMaxDynamicSharedMemorySize, smem);
    segmax_kernel<<<dim3(NCHUNK, BDIM), 256, smem>>>(enc, masks);

    mlp_kernel<<<dim3(4, BDIM), 256>>>(W1, b1, W2, b2, out);
}